// round 4
// baseline (speedup 1.0000x reference)
#include <cuda_runtime.h>
#include <math.h>

// ---------------- problem constants ----------------
constexpr int N_NODES = 10000;
constexpr int N_EDGES = 160000;
constexpr int B       = 8;
constexpr int T_IN    = 12;
constexpr int HP      = 64;
constexpr int HV      = 32;
constexpr int CDIM    = 2 * HP + 1;   // 129
constexpr int NB      = N_NODES * B;  // 80000
constexpr int EB      = N_EDGES * B;  // 1280000

// ---------------- device scratch (static; no allocation) ----------------
__device__ float4       g_node[NB];     // per (node,b): P, R, S, Q
__device__ float        g_att[EB];      // a, then reused as ex
__device__ float        g_dsum[EB];     // sum_k diff*feature[src]
__device__ unsigned int g_amax[NB];     // ordered-uint encoded float max
__device__ float        g_den[NB];      // softmax denominator
__device__ float        g_gw[CDIM];     // ln2_g * attn_w
__device__ float        g_GC[2];        // [0]=sum(g*w), [1]=sum(b*w)
__device__ float        g_xv[2 * EB];   // [0..EB): x_up ; [EB..2EB): x_dn

// ---------------- packed f32x2 helpers (sm_103a) ----------------
union F2U { float2 f; unsigned long long u; };

__device__ __forceinline__ float2 ffma2(float2 a, float2 b, float2 c) {
    F2U A, Bv, C, D; A.f = a; Bv.f = b; C.f = c;
    asm("fma.rn.f32x2 %0, %1, %2, %3;" : "=l"(D.u) : "l"(A.u), "l"(Bv.u), "l"(C.u));
    return D.f;
}
__device__ __forceinline__ float2 add2(float2 a, float2 b) {
    F2U A, Bv, D; A.f = a; Bv.f = b;
    asm("add.rn.f32x2 %0, %1, %2;" : "=l"(D.u) : "l"(A.u), "l"(Bv.u));
    return D.f;
}
__device__ __forceinline__ float2 mul2(float2 a, float2 b) {
    F2U A, Bv, D; A.f = a; Bv.f = b;
    asm("mul.rn.f32x2 %0, %1, %2;" : "=l"(D.u) : "l"(A.u), "l"(Bv.u));
    return D.f;
}

// ---------------- ordered-float atomicMax helpers ----------------
__device__ __forceinline__ unsigned int f2ord(float f) {
    unsigned int u = __float_as_uint(f);
    return (u & 0x80000000u) ? ~u : (u | 0x80000000u);
}
__device__ __forceinline__ float ord2f(unsigned int u) {
    return (u & 0x80000000u) ? __uint_as_float(u & 0x7FFFFFFFu)
                             : __uint_as_float(~u);
}

// ---------------- prep: gw = ln2_g*attn_w; G = sum(gw); C = sum(ln2_b*attn_w) --------
__global__ void prep_kernel(const float* __restrict__ ln2g,
                            const float* __restrict__ ln2b,
                            const float* __restrict__ attnw) {
    __shared__ float sG[256];
    __shared__ float sC[256];
    int t = threadIdx.x;
    float gv = 0.f, cv = 0.f;
    if (t < CDIM) {
        float w = attnw[t];
        gv = ln2g[t] * w;
        cv = ln2b[t] * w;
        g_gw[t] = gv;
    }
    sG[t] = gv; sC[t] = cv;
    __syncthreads();
    for (int s = 128; s > 0; s >>= 1) {
        if (t < s) { sG[t] += sG[t + s]; sC[t] += sC[t + s]; }
        __syncthreads();
    }
    if (t == 0) { g_GC[0] = sG[0]; g_GC[1] = sC[0]; }
}

// ---------------- init: zero pred, den, amax ----------------
__global__ void init_kernel(float* __restrict__ out) {
    int t = blockIdx.x * blockDim.x + threadIdx.x;
    if (t < NB) {
        out[t]    = 0.f;
        g_den[t]  = 0.f;
        g_amax[t] = 0u;
    }
}

// ---------------- node kernel: fold z into (P,R,S,Q) ----------------
__global__ __launch_bounds__(128)
void node_kernel(const float* __restrict__ feat,
                 const float* __restrict__ fcw) {
    __shared__ float sw[HP * T_IN];   // 768
    __shared__ float sgw[2 * HP];     // 128
    int tid = threadIdx.x;
    for (int i = tid; i < HP * T_IN; i += blockDim.x) sw[i]  = fcw[i];
    for (int i = tid; i < 2 * HP;    i += blockDim.x) sgw[i] = g_gw[i];
    __syncthreads();

    int t = blockIdx.x * blockDim.x + tid;
    if (t >= NB) return;

    float fr[T_IN];
    {
        const float4* f4 = reinterpret_cast<const float4*>(feat) + (size_t)t * 3;
        float4 a0 = f4[0], a1 = f4[1], a2 = f4[2];
        fr[0]=a0.x; fr[1]=a0.y; fr[2]=a0.z;  fr[3]=a0.w;
        fr[4]=a1.x; fr[5]=a1.y; fr[6]=a1.z;  fr[7]=a1.w;
        fr[8]=a2.x; fr[9]=a2.y; fr[10]=a2.z; fr[11]=a2.w;
    }

    float P = 0.f, R = 0.f, S = 0.f, Q = 0.f;
#pragma unroll
    for (int h = 0; h < HP; ++h) {
        float z = 0.f;
#pragma unroll
        for (int k = 0; k < T_IN; ++k) z = fmaf(sw[h * T_IN + k], fr[k], z);
        P = fmaf(z, sgw[h], P);
        R = fmaf(z, sgw[HP + h], R);
        S += z;
        Q = fmaf(z, z, Q);
    }
    g_node[t] = make_float4(P, R, S, Q);
}

// ---------------- velocity kernel: one thread = (edge, batch-pair), one branch ------
// computes sigmoid(w2 . relu(LN(W1 in + b1)) + b2) for 2 batch elems packed in f32x2
__global__ __launch_bounds__(256, 2)
void vel_kernel(const float* __restrict__ inp,
                const float* __restrict__ w1, const float* __restrict__ b1,
                const float* __restrict__ lg, const float* __restrict__ lb,
                const float* __restrict__ w2, const float* __restrict__ b2p,
                int out_base /* in float2 units */) {
    __shared__ float2 sw1[HV * T_IN];   // duplicated weight pairs (3 KB)
    __shared__ float2 sb1[HV], slg[HV], slb[HV], sw2[HV];
    __shared__ float  sb2;
    int tid = threadIdx.x;
    for (int i = tid; i < HV * T_IN; i += 256) { float w = w1[i]; sw1[i] = make_float2(w, w); }
    if (tid < HV) {
        float b = b1[tid]; sb1[tid] = make_float2(b, b);
        float g = lg[tid]; slg[tid] = make_float2(g, g);
        float q = lb[tid]; slb[tid] = make_float2(q, q);
        float w = w2[tid]; sw2[tid] = make_float2(w, w);
    }
    if (tid == 0) sb2 = b2p[0];
    __syncthreads();

    int t = blockIdx.x * 256 + tid;            // t < EB/2
    const float4* f4 = reinterpret_cast<const float4*>(inp) + (size_t)t * 6;
    float4 a0 = f4[0], a1 = f4[1], a2 = f4[2]; // batch elem 0 (12 floats)
    float4 a3 = f4[3], a4 = f4[4], a5 = f4[5]; // batch elem 1

    float2 in2[T_IN] = {
        {a0.x, a3.x}, {a0.y, a3.y}, {a0.z, a3.z}, {a0.w, a3.w},
        {a1.x, a4.x}, {a1.y, a4.y}, {a1.z, a4.z}, {a1.w, a4.w},
        {a2.x, a5.x}, {a2.y, a5.y}, {a2.z, a5.z}, {a2.w, a5.w}};

    const float4* sw14 = reinterpret_cast<const float4*>(sw1);

    float2 h2[HV];
#pragma unroll
    for (int j = 0; j < HV; ++j) {
        float2 acc = sb1[j];
#pragma unroll
        for (int kk = 0; kk < 6; ++kk) {
            float4 wp = sw14[j * 6 + kk];              // (w_k,w_k,w_k+1,w_k+1)
            acc = ffma2(make_float2(wp.x, wp.y), in2[2 * kk],     acc);
            acc = ffma2(make_float2(wp.z, wp.w), in2[2 * kk + 1], acc);
        }
        h2[j] = acc;
    }

    // LayerNorm across HV (per packed component)
    float2 sum = make_float2(0.f, 0.f);
#pragma unroll
    for (int j = 0; j < HV; ++j) sum = add2(sum, h2[j]);
    float2 mean  = mul2(sum, make_float2(1.0f / HV, 1.0f / HV));
    float2 nmean = make_float2(-mean.x, -mean.y);
    float2 var   = make_float2(0.f, 0.f);
#pragma unroll
    for (int j = 0; j < HV; ++j) {
        float2 d = add2(h2[j], nmean);
        var = ffma2(d, d, var);
    }
    float2 inv = make_float2(rsqrtf(var.x * (1.0f / HV) + 1e-5f),
                             rsqrtf(var.y * (1.0f / HV) + 1e-5f));
    float2 s = make_float2(sb2, sb2);
#pragma unroll
    for (int j = 0; j < HV; ++j) {
        float2 d  = add2(h2[j], nmean);
        float2 yn = mul2(d, inv);
        float2 y  = ffma2(yn, slg[j], slb[j]);
        y.x = fmaxf(y.x, 0.f); y.y = fmaxf(y.y, 0.f);
        s = ffma2(y, sw2[j], s);
    }
    float2 o;
    o.x = __fdividef(1.0f, 1.0f + __expf(-s.x));
    o.y = __fdividef(1.0f, 1.0f + __expf(-s.y));
    reinterpret_cast<float2*>(g_xv)[out_base + t] = o;
}

// ---------------- edge attention + diffusion kernel ----------------
__global__ __launch_bounds__(256)
void edgeA_kernel(const float* __restrict__ dist,
                  const float* __restrict__ alpha,
                  const float* __restrict__ feat,
                  const int* __restrict__ src,
                  const int* __restrict__ dst,
                  const float* __restrict__ l3w,
                  const float* __restrict__ l3b) {
    __shared__ float c[7];
    if (threadIdx.x == 0) {
        c[0] = l3w[0]; c[1] = l3w[1]; c[2] = l3w[2]; c[3] = l3b[0];
        c[4] = g_gw[128]; c[5] = g_GC[0]; c[6] = g_GC[1];
    }
    __syncthreads();

    int t = blockIdx.x * 256 + threadIdx.x;
    if (t >= EB) return;
    int e = t >> 3;
    int b = t & 7;

    float xup = g_xv[t];
    float xdn = g_xv[EB + t];
    float al  = alpha[e];

    float xv = c[0] * xup + c[1] * xdn + c[2] * al + c[3];
    // stable softplus, then clamp
    float v = (xv > 0.f) ? (xv + __logf(1.0f + __expf(-xv)))
                         : __logf(1.0f + __expf(xv));
    v = fminf(v, 3.0f);
    float Tt = __fdividef(dist[e], v + 1e-5f);

    float Tidx = fminf(fmaxf(rintf(Tt * 0.1f), 0.0f), 11.0f);
    int   n    = T_IN - (int)Tidx;                  // 1..12
    float alc  = fminf(fmaxf(al, 0.f), 1.f);
    float F    = __fdividef(1.0f, 1.0f + alc * Tt);
    float omF  = 1.0f - F;

    int se = src[e];
    int de = dst[e];

    // diffusion dot with gathered feature[src]
    float f[T_IN];
    {
        const float4* f4 = reinterpret_cast<const float4*>(feat)
                           + ((size_t)se * B + b) * 3;
        float4 q0 = f4[0], q1 = f4[1], q2 = f4[2];
        f[0]=q0.x; f[1]=q0.y; f[2]=q0.z;  f[3]=q0.w;
        f[4]=q1.x; f[5]=q1.y; f[6]=q1.z;  f[7]=q1.w;
        f[8]=q2.x; f[9]=q2.y; f[10]=q2.z; f[11]=q2.w;
    }
    float acc = 0.f, pw = 0.f;
#pragma unroll
    for (int k = T_IN - 1; k >= 0; --k) {
        if (k == n - 1) pw = F;
        if (k <= n - 1) { acc = fmaf(pw, f[k], acc); pw *= omF; }
    }

    // attention score from folded node stats
    float4 ns = g_node[se * B + b];
    float4 nd = g_node[de * B + b];
    float Ssum = ns.z + nd.z + Tt;
    float m    = Ssum * (1.0f / 129.0f);
    float q    = ns.w + nd.w + Tt * Tt;
    float var  = q * (1.0f / 129.0f) - m * m;
    float dot  = ns.x + nd.y + Tt * c[4];
    float a    = (dot - m * c[5]) * rsqrtf(var + 1e-5f) + c[6];
    a = (a >= 0.f) ? a : 0.01f * a;                 // leaky_relu

    g_att[t]  = a;
    g_dsum[t] = acc;
    atomicMax(&g_amax[se * B + b], f2ord(a));
}

// ---------------- edge pass 2: ex = exp(a - amax[src]); den[src] += ex --------------
__global__ __launch_bounds__(256)
void edge2_kernel(const int* __restrict__ src) {
    int t = blockIdx.x * 256 + threadIdx.x;
    if (t >= EB) return;
    int e = t >> 3, b = t & 7;
    int se = src[e];
    float amax = ord2f(g_amax[se * B + b]);
    float ex = __expf(g_att[t] - amax);
    g_att[t] = ex;
    atomicAdd(&g_den[se * B + b], ex);
}

// ---------------- edge pass 3: pred[dst] += ex/den[src] * dsum ----------------
__global__ __launch_bounds__(256)
void edge3_kernel(const int* __restrict__ src, const int* __restrict__ dst,
                  float* __restrict__ out) {
    int t = blockIdx.x * 256 + threadIdx.x;
    if (t >= EB) return;
    int e = t >> 3, b = t & 7;
    int se = src[e];
    int de = dst[e];
    float val = __fdividef(g_att[t], g_den[se * B + b]) * g_dsum[t];
    atomicAdd(&out[de * B + b], val);
}

// ---------------- launch ----------------
extern "C" void kernel_launch(void* const* d_in, const int* in_sizes, int n_in,
                              void* d_out, int out_size) {
    bool sig_order = (n_in >= 6 && in_sizes[5] == HP * T_IN);   // fc_w=768 at idx 5

    int i_src, i_dst, i_alpha, i_fcw, i_ln2g, i_ln2b, i_attnw;
    int i_l11w, i_l11b, i_ln11g, i_ln11b, i_l12w, i_l12b;
    int i_l21w, i_l21b, i_ln21g, i_ln21b, i_l22w, i_l22b, i_l3w, i_l3b;

    if (!sig_order) {
        i_src = 4;  i_dst = 5;  i_alpha = 6;  i_fcw = 7;
        i_ln2g = 8; i_ln2b = 9; i_attnw = 10;
        i_l11w = 11; i_l11b = 12; i_ln11g = 13; i_ln11b = 14; i_l12w = 15; i_l12b = 16;
        i_l21w = 17; i_l21b = 18; i_ln21g = 19; i_ln21b = 20; i_l22w = 21; i_l22b = 22;
        i_l3w = 23;  i_l3b = 24;
    } else {
        i_alpha = 4; i_fcw = 5;
        i_ln2g = 6;  i_ln2b = 7; i_attnw = 8;
        i_l11w = 9;  i_l11b = 10; i_ln11g = 11; i_ln11b = 12; i_l12w = 13; i_l12b = 14;
        i_l21w = 15; i_l21b = 16; i_ln21g = 17; i_ln21b = 18; i_l22w = 19; i_l22b = 20;
        i_l3w = 21;  i_l3b = 22;  i_src = 23;   i_dst = 24;
    }

    const float* feat  = (const float*)d_in[0];
    const float* up    = (const float*)d_in[1];
    const float* dn    = (const float*)d_in[2];
    const float* dist  = (const float*)d_in[3];
    const float* alpha = (const float*)d_in[i_alpha];
    const int*   src   = (const int*)d_in[i_src];
    const int*   dst   = (const int*)d_in[i_dst];
    float* out = (float*)d_out;

    prep_kernel<<<1, 256>>>((const float*)d_in[i_ln2g],
                            (const float*)d_in[i_ln2b],
                            (const float*)d_in[i_attnw]);

    init_kernel<<<(NB + 255) / 256, 256>>>(out);

    node_kernel<<<NB / 128, 128>>>(feat, (const float*)d_in[i_fcw]);

    // velocity branches: EB/2 threads each (batch-pair packed), 2500 blocks
    vel_kernel<<<(EB / 2) / 256, 256>>>(
        up,
        (const float*)d_in[i_l11w], (const float*)d_in[i_l11b],
        (const float*)d_in[i_ln11g], (const float*)d_in[i_ln11b],
        (const float*)d_in[i_l12w], (const float*)d_in[i_l12b],
        0);
    vel_kernel<<<(EB / 2) / 256, 256>>>(
        dn,
        (const float*)d_in[i_l21w], (const float*)d_in[i_l21b],
        (const float*)d_in[i_ln21g], (const float*)d_in[i_ln21b],
        (const float*)d_in[i_l22w], (const float*)d_in[i_l22b],
        EB / 2);

    edgeA_kernel<<<EB / 256, 256>>>(dist, alpha, feat, src, dst,
                                    (const float*)d_in[i_l3w],
                                    (const float*)d_in[i_l3b]);
    edge2_kernel<<<EB / 256, 256>>>(src);
    edge3_kernel<<<EB / 256, 256>>>(src, dst, out);
}

// round 5
// speedup vs baseline: 1.0572x; 1.0572x over previous
#include <cuda_runtime.h>
#include <math.h>

// ---------------- problem constants ----------------
constexpr int N_NODES = 10000;
constexpr int N_EDGES = 160000;
constexpr int B       = 8;
constexpr int T_IN    = 12;
constexpr int HP      = 64;
constexpr int HV      = 32;
constexpr int CDIM    = 2 * HP + 1;   // 129
constexpr int NB      = N_NODES * B;  // 80000
constexpr int EB      = N_EDGES * B;  // 1280000

// ---------------- device scratch (static; no allocation) ----------------
__device__ float4       g_node[NB];     // per (node,b): P, R, S, Q
__device__ float        g_att[EB];      // a, then reused as ex
__device__ float        g_dsum[EB];     // sum_k diff*feature[src]
__device__ unsigned int g_amax[NB];     // ordered-uint encoded float max
__device__ float        g_den[NB];      // softmax denominator
__device__ float        g_gw[CDIM];     // ln2_g * attn_w
__device__ float        g_GC[2];        // [0]=sum(g*w), [1]=sum(b*w)
__device__ float        g_xv[2 * EB];   // [0..EB): x_up ; [EB..2EB): x_dn

// ---------------- packed f32x2 helpers: values live in u64 regs ----------------
using U64 = unsigned long long;

__device__ __forceinline__ U64 ffma2(U64 a, U64 b, U64 c) {
    U64 d;
    asm("fma.rn.f32x2 %0, %1, %2, %3;" : "=l"(d) : "l"(a), "l"(b), "l"(c));
    return d;
}
__device__ __forceinline__ U64 add2(U64 a, U64 b) {
    U64 d;
    asm("add.rn.f32x2 %0, %1, %2;" : "=l"(d) : "l"(a), "l"(b));
    return d;
}
__device__ __forceinline__ U64 mul2(U64 a, U64 b) {
    U64 d;
    asm("mul.rn.f32x2 %0, %1, %2;" : "=l"(d) : "l"(a), "l"(b));
    return d;
}
__device__ __forceinline__ U64 pack2(float lo, float hi) {
    U64 d;
    asm("mov.b64 %0, {%1, %2};" : "=l"(d) : "f"(lo), "f"(hi));
    return d;
}
__device__ __forceinline__ void unpack2(U64 v, float& lo, float& hi) {
    asm("mov.b64 {%0, %1}, %2;" : "=f"(lo), "=f"(hi) : "l"(v));
}

// ---------------- ordered-float atomicMax helpers ----------------
__device__ __forceinline__ unsigned int f2ord(float f) {
    unsigned int u = __float_as_uint(f);
    return (u & 0x80000000u) ? ~u : (u | 0x80000000u);
}
__device__ __forceinline__ float ord2f(unsigned int u) {
    return (u & 0x80000000u) ? __uint_as_float(u & 0x7FFFFFFFu)
                             : __uint_as_float(~u);
}

// ---------------- prep: gw = ln2_g*attn_w; G = sum(gw); C = sum(ln2_b*attn_w) --------
__global__ void prep_kernel(const float* __restrict__ ln2g,
                            const float* __restrict__ ln2b,
                            const float* __restrict__ attnw) {
    __shared__ float sG[256];
    __shared__ float sC[256];
    int t = threadIdx.x;
    float gv = 0.f, cv = 0.f;
    if (t < CDIM) {
        float w = attnw[t];
        gv = ln2g[t] * w;
        cv = ln2b[t] * w;
        g_gw[t] = gv;
    }
    sG[t] = gv; sC[t] = cv;
    __syncthreads();
    for (int s = 128; s > 0; s >>= 1) {
        if (t < s) { sG[t] += sG[t + s]; sC[t] += sC[t + s]; }
        __syncthreads();
    }
    if (t == 0) { g_GC[0] = sG[0]; g_GC[1] = sC[0]; }
}

// ---------------- init: zero pred, den, amax ----------------
__global__ void init_kernel(float* __restrict__ out) {
    int t = blockIdx.x * blockDim.x + threadIdx.x;
    if (t < NB) {
        out[t]    = 0.f;
        g_den[t]  = 0.f;
        g_amax[t] = 0u;
    }
}

// ---------------- node kernel: fold z into (P,R,S,Q) ----------------
__global__ __launch_bounds__(128)
void node_kernel(const float* __restrict__ feat,
                 const float* __restrict__ fcw) {
    __shared__ float sw[HP * T_IN];   // 768
    __shared__ float sgw[2 * HP];     // 128
    int tid = threadIdx.x;
    for (int i = tid; i < HP * T_IN; i += blockDim.x) sw[i]  = fcw[i];
    for (int i = tid; i < 2 * HP;    i += blockDim.x) sgw[i] = g_gw[i];
    __syncthreads();

    int t = blockIdx.x * blockDim.x + tid;
    if (t >= NB) return;

    float fr[T_IN];
    {
        const float4* f4 = reinterpret_cast<const float4*>(feat) + (size_t)t * 3;
        float4 a0 = f4[0], a1 = f4[1], a2 = f4[2];
        fr[0]=a0.x; fr[1]=a0.y; fr[2]=a0.z;  fr[3]=a0.w;
        fr[4]=a1.x; fr[5]=a1.y; fr[6]=a1.z;  fr[7]=a1.w;
        fr[8]=a2.x; fr[9]=a2.y; fr[10]=a2.z; fr[11]=a2.w;
    }

    float P = 0.f, R = 0.f, S = 0.f, Q = 0.f;
#pragma unroll
    for (int h = 0; h < HP; ++h) {
        float z = 0.f;
#pragma unroll
        for (int k = 0; k < T_IN; ++k) z = fmaf(sw[h * T_IN + k], fr[k], z);
        P = fmaf(z, sgw[h], P);
        R = fmaf(z, sgw[HP + h], R);
        S += z;
        Q = fmaf(z, z, Q);
    }
    g_node[t] = make_float4(P, R, S, Q);
}

// ---------------- velocity kernel: one thread = (edge, batch-pair), one branch ------
// sigmoid(w2 . relu(LN(W1 in + b1)) + b2) for 2 batch elems packed in f32x2 (u64 regs)
__global__ __launch_bounds__(256, 2)
void vel_kernel(const float* __restrict__ inp,
                const float* __restrict__ w1, const float* __restrict__ b1,
                const float* __restrict__ lg, const float* __restrict__ lb,
                const float* __restrict__ w2, const float* __restrict__ b2p,
                int out_base /* in float2 units */) {
    // duplicated weight pairs, 16B-aligned so LDS.128 yields ready u64 halves
    __shared__ __align__(16) float2 swp[HV * T_IN];   // (w,w) pairs, 3 KB
    __shared__ __align__(8)  float2 sb1u[HV], slgu[HV], slbu[HV];
    __shared__ float sw2s[HV];
    __shared__ float sb2;
    int tid = threadIdx.x;
    for (int i = tid; i < HV * T_IN; i += 256) { float w = w1[i]; swp[i] = make_float2(w, w); }
    if (tid < HV) {
        float b = b1[tid]; sb1u[tid] = make_float2(b, b);
        float g = lg[tid]; slgu[tid] = make_float2(g, g);
        float q = lb[tid]; slbu[tid] = make_float2(q, q);
        sw2s[tid] = w2[tid];
    }
    if (tid == 0) sb2 = b2p[0];
    __syncthreads();

    int t = blockIdx.x * 256 + tid;            // t < EB/2
    const float4* f4 = reinterpret_cast<const float4*>(inp) + (size_t)t * 6;
    float4 a0 = f4[0], a1 = f4[1], a2 = f4[2]; // batch elem 0 (12 floats)
    float4 a3 = f4[3], a4 = f4[4], a5 = f4[5]; // batch elem 1

    U64 in2[T_IN];
    in2[0]  = pack2(a0.x, a3.x); in2[1]  = pack2(a0.y, a3.y);
    in2[2]  = pack2(a0.z, a3.z); in2[3]  = pack2(a0.w, a3.w);
    in2[4]  = pack2(a1.x, a4.x); in2[5]  = pack2(a1.y, a4.y);
    in2[6]  = pack2(a1.z, a4.z); in2[7]  = pack2(a1.w, a4.w);
    in2[8]  = pack2(a2.x, a5.x); in2[9]  = pack2(a2.y, a5.y);
    in2[10] = pack2(a2.z, a5.z); in2[11] = pack2(a2.w, a5.w);

    const ulonglong2* sw2v = reinterpret_cast<const ulonglong2*>(swp);
    const U64* sb1v = reinterpret_cast<const U64*>(sb1u);
    const U64* slgv = reinterpret_cast<const U64*>(slgu);
    const U64* slbv = reinterpret_cast<const U64*>(slbu);

    U64 h[HV];
#pragma unroll
    for (int j = 0; j < HV; ++j) {
        U64 acc = sb1v[j];
#pragma unroll
        for (int kk = 0; kk < 6; ++kk) {
            ulonglong2 wp = sw2v[j * 6 + kk];     // (w_2k,w_2k) | (w_2k+1,w_2k+1)
            acc = ffma2(wp.x, in2[2 * kk],     acc);
            acc = ffma2(wp.y, in2[2 * kk + 1], acc);
        }
        h[j] = acc;
    }

    // LayerNorm across HV (per packed component), pairwise-ish reduction
    U64 s0 = add2(h[0], h[1]);
    U64 s1 = add2(h[2], h[3]);
#pragma unroll
    for (int j = 4; j < HV; j += 4) {
        s0 = add2(s0, add2(h[j],     h[j + 1]));
        s1 = add2(s1, add2(h[j + 2], h[j + 3]));
    }
    U64 sum = add2(s0, s1);
    U64 mean  = mul2(sum, pack2(1.0f / HV, 1.0f / HV));
    U64 nmean = mul2(mean, pack2(-1.0f, -1.0f));
    U64 var = pack2(0.f, 0.f);
#pragma unroll
    for (int j = 0; j < HV; ++j) {
        U64 d = add2(h[j], nmean);
        h[j] = d;                                   // keep centered value
        var = ffma2(d, d, var);
    }
    float v0, v1;
    unpack2(var, v0, v1);
    float i0 = rsqrtf(v0 * (1.0f / HV) + 1e-5f);
    float i1 = rsqrtf(v1 * (1.0f / HV) + 1e-5f);
    U64 inv = pack2(i0, i1);

    float acc0 = sb2, acc1 = sb2;
#pragma unroll
    for (int j = 0; j < HV; ++j) {
        U64 sc = mul2(inv, slgv[j]);
        U64 y  = ffma2(h[j], sc, slbv[j]);
        float y0, y1;
        unpack2(y, y0, y1);
        y0 = fmaxf(y0, 0.f); y1 = fmaxf(y1, 0.f);
        float w = sw2s[j];
        acc0 = fmaf(y0, w, acc0);
        acc1 = fmaf(y1, w, acc1);
    }
    float2 o;
    o.x = __fdividef(1.0f, 1.0f + __expf(-acc0));
    o.y = __fdividef(1.0f, 1.0f + __expf(-acc1));
    reinterpret_cast<float2*>(g_xv)[out_base + t] = o;
}

// ---------------- edge attention + diffusion kernel ----------------
__global__ __launch_bounds__(256)
void edgeA_kernel(const float* __restrict__ dist,
                  const float* __restrict__ alpha,
                  const float* __restrict__ feat,
                  const int* __restrict__ src,
                  const int* __restrict__ dst,
                  const float* __restrict__ l3w,
                  const float* __restrict__ l3b) {
    __shared__ float c[7];
    if (threadIdx.x == 0) {
        c[0] = l3w[0]; c[1] = l3w[1]; c[2] = l3w[2]; c[3] = l3b[0];
        c[4] = g_gw[128]; c[5] = g_GC[0]; c[6] = g_GC[1];
    }
    __syncthreads();

    int t = blockIdx.x * 256 + threadIdx.x;
    if (t >= EB) return;
    int e = t >> 3;
    int b = t & 7;

    float xup = g_xv[t];
    float xdn = g_xv[EB + t];
    float al  = alpha[e];

    float xv = c[0] * xup + c[1] * xdn + c[2] * al + c[3];
    float v = (xv > 0.f) ? (xv + __logf(1.0f + __expf(-xv)))
                         : __logf(1.0f + __expf(xv));
    v = fminf(v, 3.0f);
    float Tt = __fdividef(dist[e], v + 1e-5f);

    float Tidx = fminf(fmaxf(rintf(Tt * 0.1f), 0.0f), 11.0f);
    int   n    = T_IN - (int)Tidx;                  // 1..12
    float alc  = fminf(fmaxf(al, 0.f), 1.f);
    float F    = __fdividef(1.0f, 1.0f + alc * Tt);
    float omF  = 1.0f - F;

    int se = src[e];
    int de = dst[e];

    float f[T_IN];
    {
        const float4* f4 = reinterpret_cast<const float4*>(feat)
                           + ((size_t)se * B + b) * 3;
        float4 q0 = f4[0], q1 = f4[1], q2 = f4[2];
        f[0]=q0.x; f[1]=q0.y; f[2]=q0.z;  f[3]=q0.w;
        f[4]=q1.x; f[5]=q1.y; f[6]=q1.z;  f[7]=q1.w;
        f[8]=q2.x; f[9]=q2.y; f[10]=q2.z; f[11]=q2.w;
    }
    float acc = 0.f, pw = 0.f;
#pragma unroll
    for (int k = T_IN - 1; k >= 0; --k) {
        if (k == n - 1) pw = F;
        if (k <= n - 1) { acc = fmaf(pw, f[k], acc); pw *= omF; }
    }

    float4 ns = g_node[se * B + b];
    float4 nd = g_node[de * B + b];
    float Ssum = ns.z + nd.z + Tt;
    float m    = Ssum * (1.0f / 129.0f);
    float q    = ns.w + nd.w + Tt * Tt;
    float var  = q * (1.0f / 129.0f) - m * m;
    float dot  = ns.x + nd.y + Tt * c[4];
    float a    = (dot - m * c[5]) * rsqrtf(var + 1e-5f) + c[6];
    a = (a >= 0.f) ? a : 0.01f * a;                 // leaky_relu

    g_att[t]  = a;
    g_dsum[t] = acc;
    atomicMax(&g_amax[se * B + b], f2ord(a));
}

// ---------------- edge pass 2: ex = exp(a - amax[src]); den[src] += ex --------------
__global__ __launch_bounds__(256)
void edge2_kernel(const int* __restrict__ src) {
    int t = blockIdx.x * 256 + threadIdx.x;
    if (t >= EB) return;
    int e = t >> 3, b = t & 7;
    int se = src[e];
    float amax = ord2f(g_amax[se * B + b]);
    float ex = __expf(g_att[t] - amax);
    g_att[t] = ex;
    atomicAdd(&g_den[se * B + b], ex);
}

// ---------------- edge pass 3: pred[dst] += ex/den[src] * dsum ----------------
__global__ __launch_bounds__(256)
void edge3_kernel(const int* __restrict__ src, const int* __restrict__ dst,
                  float* __restrict__ out) {
    int t = blockIdx.x * 256 + threadIdx.x;
    if (t >= EB) return;
    int e = t >> 3, b = t & 7;
    int se = src[e];
    int de = dst[e];
    float val = __fdividef(g_att[t], g_den[se * B + b]) * g_dsum[t];
    atomicAdd(&out[de * B + b], val);
}

// ---------------- launch ----------------
extern "C" void kernel_launch(void* const* d_in, const int* in_sizes, int n_in,
                              void* d_out, int out_size) {
    bool sig_order = (n_in >= 6 && in_sizes[5] == HP * T_IN);   // fc_w=768 at idx 5

    int i_src, i_dst, i_alpha, i_fcw, i_ln2g, i_ln2b, i_attnw;
    int i_l11w, i_l11b, i_ln11g, i_ln11b, i_l12w, i_l12b;
    int i_l21w, i_l21b, i_ln21g, i_ln21b, i_l22w, i_l22b, i_l3w, i_l3b;

    if (!sig_order) {
        i_src = 4;  i_dst = 5;  i_alpha = 6;  i_fcw = 7;
        i_ln2g = 8; i_ln2b = 9; i_attnw = 10;
        i_l11w = 11; i_l11b = 12; i_ln11g = 13; i_ln11b = 14; i_l12w = 15; i_l12b = 16;
        i_l21w = 17; i_l21b = 18; i_ln21g = 19; i_ln21b = 20; i_l22w = 21; i_l22b = 22;
        i_l3w = 23;  i_l3b = 24;
    } else {
        i_alpha = 4; i_fcw = 5;
        i_ln2g = 6;  i_ln2b = 7; i_attnw = 8;
        i_l11w = 9;  i_l11b = 10; i_ln11g = 11; i_ln11b = 12; i_l12w = 13; i_l12b = 14;
        i_l21w = 15; i_l21b = 16; i_ln21g = 17; i_ln21b = 18; i_l22w = 19; i_l22b = 20;
        i_l3w = 21;  i_l3b = 22;  i_src = 23;   i_dst = 24;
    }

    const float* feat  = (const float*)d_in[0];
    const float* up    = (const float*)d_in[1];
    const float* dn    = (const float*)d_in[2];
    const float* dist  = (const float*)d_in[3];
    const float* alpha = (const float*)d_in[i_alpha];
    const int*   src   = (const int*)d_in[i_src];
    const int*   dst   = (const int*)d_in[i_dst];
    float* out = (float*)d_out;

    prep_kernel<<<1, 256>>>((const float*)d_in[i_ln2g],
                            (const float*)d_in[i_ln2b],
                            (const float*)d_in[i_attnw]);

    init_kernel<<<(NB + 255) / 256, 256>>>(out);

    node_kernel<<<NB / 128, 128>>>(feat, (const float*)d_in[i_fcw]);

    vel_kernel<<<(EB / 2) / 256, 256>>>(
        up,
        (const float*)d_in[i_l11w], (const float*)d_in[i_l11b],
        (const float*)d_in[i_ln11g], (const float*)d_in[i_ln11b],
        (const float*)d_in[i_l12w], (const float*)d_in[i_l12b],
        0);
    vel_kernel<<<(EB / 2) / 256, 256>>>(
        dn,
        (const float*)d_in[i_l21w], (const float*)d_in[i_l21b],
        (const float*)d_in[i_ln21g], (const float*)d_in[i_ln21b],
        (const float*)d_in[i_l22w], (const float*)d_in[i_l22b],
        EB / 2);

    edgeA_kernel<<<EB / 256, 256>>>(dist, alpha, feat, src, dst,
                                    (const float*)d_in[i_l3w],
                                    (const float*)d_in[i_l3b]);
    edge2_kernel<<<EB / 256, 256>>>(src);
    edge3_kernel<<<EB / 256, 256>>>(src, dst, out);
}